// round 1
// baseline (speedup 1.0000x reference)
#include <cuda_runtime.h>
#include <math.h>

// Problem constants (fixed by reference: x (64,512,512), codebooks (6,1024,512))
#define NB 64
#define CC 512
#define TT 512
#define NT (NB * TT)   // 32768 rows
#define KK 1024        // codes per stage
#define QQ 6           // stages

// ---------------- scratch (static __device__ globals; no allocation) --------
__device__ float  g_res[(size_t)NT * CC];   // residual, row-major (NT, C)  64 MB
__device__ float  g_cbnorm[QQ * KK];        // ||c_k||^2 per stage
__device__ int    g_counts[QQ * KK];        // code usage histogram per stage
__device__ double g_loss[QQ];               // sum of new-residual^2 per stage

// ---------------- init: zero counts / loss ---------------------------------
__global__ void init_kernel() {
    int t = blockIdx.x * blockDim.x + threadIdx.x;
    if (t < QQ * KK) g_counts[t] = 0;
    if (t < QQ)      g_loss[t]   = 0.0;
}

// ---------------- codebook norms: one warp per code row --------------------
__global__ void cbnorm_kernel(const float* __restrict__ cbs) {
    int warp = (blockIdx.x * blockDim.x + threadIdx.x) >> 5;
    int lane = threadIdx.x & 31;
    if (warp >= QQ * KK) return;
    const float* row = cbs + (size_t)warp * CC;
    float s = 0.f;
    #pragma unroll 4
    for (int c = lane; c < CC; c += 32) { float v = row[c]; s += v * v; }
    #pragma unroll
    for (int off = 16; off > 0; off >>= 1)
        s += __shfl_xor_sync(0xffffffffu, s, off);
    if (lane == 0) g_cbnorm[warp] = s;
}

// ---------------- transpose x (N,C,T) -> res (N*T, C) ----------------------
__global__ void transpose_in_kernel(const float* __restrict__ x) {
    __shared__ float tile[32][33];
    int n = blockIdx.z;
    int t0 = blockIdx.x * 32, c0 = blockIdx.y * 32;
    int tx = threadIdx.x;
    #pragma unroll
    for (int i = threadIdx.y; i < 32; i += 8)
        tile[i][tx] = x[(size_t)n * CC * TT + (size_t)(c0 + i) * TT + t0 + tx];
    __syncthreads();
    #pragma unroll
    for (int i = threadIdx.y; i < 32; i += 8)
        g_res[(size_t)(n * TT + t0 + i) * CC + c0 + tx] = tile[tx][i];
}

// ---------------- fused stage: GEMM + argmin + update + stats --------------
// Block: 256 threads (tx=tid&15 over codes, ty=tid>>4 over rows).
// BM=64 rows/block, BN=128 codes/tile (2 groups of tx*4), BK=32, TM=4, TN=8.
__global__ void __launch_bounds__(256, 2)
vq_stage_kernel(const float* __restrict__ cb,   // this stage's codebook (K, C)
                float* __restrict__ idx_out,    // d_out + NT*CC, layout (NT, Q)
                int q) {
    __shared__ float As[32][64];     // k-major residual tile
    __shared__ float Bs[32][128];    // k-major codebook tile
    __shared__ int   sBest[64];
    __shared__ float sRed[256];

    const int tid = threadIdx.x;
    const int tx = tid & 15, ty = tid >> 4;
    const int r0 = blockIdx.x * 64;

    float bestd[4];
    int   besti[4];
    #pragma unroll
    for (int i = 0; i < 4; i++) { bestd[i] = 3.4e38f; besti[i] = 0; }

    for (int nt = 0; nt < KK / 128; ++nt) {
        const int n0 = nt * 128;
        float acc[4][8];
        #pragma unroll
        for (int i = 0; i < 4; i++)
            #pragma unroll
            for (int j = 0; j < 8; j++) acc[i][j] = 0.f;

        for (int kc = 0; kc < CC / 32; ++kc) {
            const int k0 = kc * 32;
            // load As: 64 rows x 32 cols = 512 float4
            #pragma unroll
            for (int l = 0; l < 2; l++) {
                int f = tid + l * 256;
                int m = f >> 3, q8 = f & 7;
                float4 v = *(const float4*)(&g_res[(size_t)(r0 + m) * CC + k0 + q8 * 4]);
                As[q8 * 4 + 0][m] = v.x; As[q8 * 4 + 1][m] = v.y;
                As[q8 * 4 + 2][m] = v.z; As[q8 * 4 + 3][m] = v.w;
            }
            // load Bs: 128 codes x 32 cols = 1024 float4
            #pragma unroll
            for (int l = 0; l < 4; l++) {
                int f = tid + l * 256;
                int n = f >> 3, q8 = f & 7;
                float4 v = *(const float4*)(&cb[(size_t)(n0 + n) * CC + k0 + q8 * 4]);
                Bs[q8 * 4 + 0][n] = v.x; Bs[q8 * 4 + 1][n] = v.y;
                Bs[q8 * 4 + 2][n] = v.z; Bs[q8 * 4 + 3][n] = v.w;
            }
            __syncthreads();
            #pragma unroll
            for (int kk = 0; kk < 32; ++kk) {
                float4 a  = *(const float4*)(&As[kk][ty * 4]);
                float4 b0 = *(const float4*)(&Bs[kk][tx * 4]);
                float4 b1 = *(const float4*)(&Bs[kk][64 + tx * 4]);
                float av[4] = {a.x, a.y, a.z, a.w};
                float bv[8] = {b0.x, b0.y, b0.z, b0.w, b1.x, b1.y, b1.z, b1.w};
                #pragma unroll
                for (int i = 0; i < 4; i++)
                    #pragma unroll
                    for (int j = 0; j < 8; j++)
                        acc[i][j] += av[i] * bv[j];
            }
            __syncthreads();
        }
        // epilogue: score = ||c||^2 - 2 r.c ; track argmin (ascending index)
        float4 na = *(const float4*)(&g_cbnorm[q * KK + n0 + tx * 4]);
        float4 nb = *(const float4*)(&g_cbnorm[q * KK + n0 + 64 + tx * 4]);
        float nav[4] = {na.x, na.y, na.z, na.w};
        float nbv[4] = {nb.x, nb.y, nb.z, nb.w};
        #pragma unroll
        for (int i = 0; i < 4; i++) {
            #pragma unroll
            for (int j = 0; j < 4; j++) {
                float s = nav[j] - 2.f * acc[i][j];
                if (s < bestd[i]) { bestd[i] = s; besti[i] = n0 + tx * 4 + j; }
            }
            #pragma unroll
            for (int j = 0; j < 4; j++) {
                float s = nbv[j] - 2.f * acc[i][j + 4];
                if (s < bestd[i]) { bestd[i] = s; besti[i] = n0 + 64 + tx * 4 + j; }
            }
        }
    }

    // reduce argmin across the 16 tx lanes (width-16 butterfly; tie -> lower idx)
    #pragma unroll
    for (int i = 0; i < 4; i++) {
        float d = bestd[i]; int bi = besti[i];
        #pragma unroll
        for (int off = 8; off > 0; off >>= 1) {
            float od = __shfl_xor_sync(0xffffffffu, d, off, 16);
            int   oi = __shfl_xor_sync(0xffffffffu, bi, off, 16);
            if (od < d || (od == d && oi < bi)) { d = od; bi = oi; }
        }
        if (tx == 0) sBest[ty * 4 + i] = bi;
    }
    __syncthreads();

    // update phase: res -= cb[best]; loss += new_res^2; histogram; index out
    float lsum = 0.f;
    #pragma unroll 4
    for (int e = tid; e < 64 * 128; e += 256) {
        int m = e >> 7;
        int c4 = (e & 127) * 4;
        int code = sBest[m];
        float4 rv = *(float4*)(&g_res[(size_t)(r0 + m) * CC + c4]);
        float4 cv = *(const float4*)(&cb[(size_t)code * CC + c4]);
        rv.x -= cv.x; rv.y -= cv.y; rv.z -= cv.z; rv.w -= cv.w;
        lsum += rv.x * rv.x + rv.y * rv.y + rv.z * rv.z + rv.w * rv.w;
        *(float4*)(&g_res[(size_t)(r0 + m) * CC + c4]) = rv;
    }
    sRed[tid] = lsum;
    __syncthreads();
    for (int s = 128; s > 0; s >>= 1) {
        if (tid < s) sRed[tid] += sRed[tid + s];
        __syncthreads();
    }
    if (tid == 0) atomicAdd(&g_loss[q], (double)sRed[0]);
    if (tid < 64) {
        int code = sBest[tid];
        atomicAdd(&g_counts[q * KK + code], 1);
        idx_out[(size_t)(r0 + tid) * QQ + q] = (float)code;
    }
}

// ---------------- output: quantized = x - res, back to (N,C,T) -------------
__global__ void output_kernel(const float* __restrict__ x, float* __restrict__ out) {
    __shared__ float tile[32][33];
    int n = blockIdx.z;
    int t0 = blockIdx.x * 32, c0 = blockIdx.y * 32;
    int tx = threadIdx.x;
    #pragma unroll
    for (int i = threadIdx.y; i < 32; i += 8)
        tile[i][tx] = g_res[(size_t)(n * TT + t0 + i) * CC + c0 + tx];
    __syncthreads();
    #pragma unroll
    for (int i = threadIdx.y; i < 32; i += 8) {
        size_t o = (size_t)n * CC * TT + (size_t)(c0 + i) * TT + t0 + tx;
        out[o] = x[o] - tile[tx][i];
    }
}

// ---------------- finalize: loss mean + perplexity mean --------------------
__global__ void finalize_kernel(float* __restrict__ out_scalars) {
    __shared__ float red[256];
    __shared__ float perp_sum_s;
    int tid = threadIdx.x;
    if (tid == 0) perp_sum_s = 0.f;
    __syncthreads();
    for (int q = 0; q < QQ; q++) {
        float h = 0.f;
        for (int k = tid; k < KK; k += 256) {
            float p = (float)g_counts[q * KK + k] / ((float)NT + 1e-10f);
            h += p * logf(p + 1e-7f);
        }
        red[tid] = h;
        __syncthreads();
        for (int s = 128; s > 0; s >>= 1) {
            if (tid < s) red[tid] += red[tid + s];
            __syncthreads();
        }
        if (tid == 0) perp_sum_s += expf(-red[0]);
        __syncthreads();
    }
    if (tid == 0) {
        double ls = 0.0;
        for (int q = 0; q < QQ; q++) ls += g_loss[q];
        out_scalars[0] = (float)(ls / (double)QQ / ((double)NT * (double)CC));
        out_scalars[1] = perp_sum_s / (float)QQ;
    }
}

// ---------------- launch ----------------------------------------------------
extern "C" void kernel_launch(void* const* d_in, const int* in_sizes, int n_in,
                              void* d_out, int out_size) {
    const float* x   = (const float*)d_in[0];   // (64, 512, 512)
    const float* cbs = (const float*)d_in[1];   // (6, 1024, 512)
    float* out = (float*)d_out;
    float* idx_out = out + (size_t)NT * CC;                       // (NT, Q) as float
    float* scalars = out + (size_t)NT * CC + (size_t)NT * QQ;     // [loss, perp]

    init_kernel<<<(QQ * KK + 255) / 256, 256>>>();
    cbnorm_kernel<<<(QQ * KK * 32 + 255) / 256, 256>>>(cbs);
    {
        dim3 g(TT / 32, CC / 32, NB), b(32, 8);
        transpose_in_kernel<<<g, b>>>(x);
    }
    for (int q = 0; q < QQ; q++) {
        const float* cb = cbs + (size_t)q * KK * CC;
        vq_stage_kernel<<<NT / 64, 256>>>(cb, idx_out, q);
    }
    {
        dim3 g(TT / 32, CC / 32, NB), b(32, 8);
        output_kernel<<<g, b>>>(x, out);
    }
    finalize_kernel<<<1, 256>>>(scalars);
}

// round 4
// speedup vs baseline: 2.3945x; 2.3945x over previous
#include <cuda_runtime.h>
#include <math.h>
#include <stdint.h>

// Problem constants (fixed): x (64,512,512), codebooks (6,1024,512)
#define NB 64
#define CC 512
#define TT 512
#define NT (NB * TT)   // 32768 rows
#define KK 1024        // codes per stage
#define QQ 6           // stages
#define DELTA 0.35f    // tf32 margin (~8 sigma of tf32 dot noise)

// GEMM tiling
#define BM 128
#define BN 128
#define BK 32
#define ASTRIDE 40     // padded smem stride (floats); 160B keeps 16B alignment

// ---------------- scratch (static __device__ globals) -----------------------
__device__ float  g_res[(size_t)NT * CC];   // residual (NT, C)
__device__ float  g_cbnorm[QQ * KK];        // ||c_k||^2
__device__ int    g_counts[QQ * KK];        // histogram
__device__ double g_loss[QQ];               // sum new-residual^2
__device__ int    g_flagcnt[QQ];            // flagged-row counts
__device__ int    g_flagged[NT];            // flagged row ids (per current stage)

// ---------------- helpers ---------------------------------------------------
__device__ __forceinline__ void cp16(uint32_t dst, const void* src) {
    asm volatile("cp.async.cg.shared.global [%0], [%1], 16;\n" :: "r"(dst), "l"(src));
}
__device__ __forceinline__ void cp_commit() { asm volatile("cp.async.commit_group;\n"); }
__device__ __forceinline__ void cp_wait0()  { asm volatile("cp.async.wait_group 0;\n"); }

__device__ __forceinline__ void mma_tf32(float* c, const uint32_t* a, const uint32_t* b) {
    asm volatile(
        "mma.sync.aligned.m16n8k8.row.col.f32.tf32.tf32.f32 "
        "{%0,%1,%2,%3},{%4,%5,%6,%7},{%8,%9},{%0,%1,%2,%3};\n"
        : "+f"(c[0]), "+f"(c[1]), "+f"(c[2]), "+f"(c[3])
        : "r"(a[0]), "r"(a[1]), "r"(a[2]), "r"(a[3]), "r"(b[0]), "r"(b[1]));
}

// track best + second-best with tie -> lower index on best
__device__ __forceinline__ void upd(float& bd, float& bs, int& bi, float d, int idx) {
    if (d < bd || (d == bd && idx < bi)) { bs = bd; bd = d; bi = idx; }
    else bs = fminf(bs, d);
}
// merge two (best,second) partitions; second = min(loser_best, winner_second)
__device__ __forceinline__ void merge2(float& bd, float& bs, int& bi,
                                       float ob, float os, int oi) {
    if (ob < bd || (ob == bd && oi < bi)) { bs = fminf(bd, os); bd = ob; bi = oi; }
    else                                  { bs = fminf(bs, ob); }
}

// ---------------- init ------------------------------------------------------
__global__ void init_kernel() {
    int t = blockIdx.x * blockDim.x + threadIdx.x;
    if (t < QQ * KK) g_counts[t] = 0;
    if (t < QQ) { g_loss[t] = 0.0; g_flagcnt[t] = 0; }
}

// ---------------- codebook norms -------------------------------------------
__global__ void cbnorm_kernel(const float* __restrict__ cbs) {
    int warp = (blockIdx.x * blockDim.x + threadIdx.x) >> 5;
    int lane = threadIdx.x & 31;
    if (warp >= QQ * KK) return;
    const float* row = cbs + (size_t)warp * CC;
    float s = 0.f;
    #pragma unroll 4
    for (int c = lane; c < CC; c += 32) { float v = row[c]; s += v * v; }
    #pragma unroll
    for (int off = 16; off > 0; off >>= 1)
        s += __shfl_xor_sync(0xffffffffu, s, off);
    if (lane == 0) g_cbnorm[warp] = s;
}

// ---------------- transpose x (N,C,T) -> res (N*T, C) ----------------------
__global__ void transpose_in_kernel(const float* __restrict__ x) {
    __shared__ float tile[32][33];
    int n = blockIdx.z;
    int t0 = blockIdx.x * 32, c0 = blockIdx.y * 32;
    int tx = threadIdx.x;
    #pragma unroll
    for (int i = threadIdx.y; i < 32; i += 8)
        tile[i][tx] = x[(size_t)n * CC * TT + (size_t)(c0 + i) * TT + t0 + tx];
    __syncthreads();
    #pragma unroll
    for (int i = threadIdx.y; i < 32; i += 8)
        g_res[(size_t)(n * TT + t0 + i) * CC + c0 + tx] = tile[tx][i];
}

// ---------------- approx stage: tf32 MMA + argmin + flag + fused update ----
extern __shared__ char smem_raw[];

__global__ void __launch_bounds__(256)
vq_approx_kernel(const float* __restrict__ cb, float* __restrict__ idx_out, int q) {
    float* As    = (float*)smem_raw;            // 2 * BM * ASTRIDE
    float* Bs    = As + 2 * BM * ASTRIDE;       // 2 * BN * ASTRIDE
    float* sNorm = Bs + 2 * BN * ASTRIDE;       // KK
    float* sD    = sNorm + KK;                  // 2*128
    float* sS    = sD + 256;                    // 2*128
    int*   sI    = (int*)(sS + 256);            // 2*128
    int*   sFi   = sI + 256;                    // 128
    int*   sFf   = sFi + 128;                   // 128
    float* sRed  = (float*)(sFf + 128);         // 256

    const int tid  = threadIdx.x;
    const int lane = tid & 31, wid = tid >> 5;
    const int wm = wid & 3, wn = wid >> 2;      // warp grid 4 x 2
    const int g = lane >> 2, tig = lane & 3;
    const int r0 = blockIdx.x * BM;

    for (int i = tid; i < KK; i += 256) sNorm[i] = g_cbnorm[q * KK + i];

    float bd[4], bs[4]; int bi[4];
    #pragma unroll
    for (int i = 0; i < 4; i++) { bd[i] = 3.4e38f; bs[i] = 3.4e38f; bi[i] = 0x7fffffff; }

    const uint32_t smemA0 = (uint32_t)__cvta_generic_to_shared(As);
    const uint32_t smemB0 = (uint32_t)__cvta_generic_to_shared(Bs);

    for (int nt = 0; nt < KK / BN; ++nt) {
        const int n0 = nt * BN;
        float acc[2][8][4];
        #pragma unroll
        for (int mf = 0; mf < 2; mf++)
            #pragma unroll
            for (int nf = 0; nf < 8; nf++)
                #pragma unroll
                for (int c = 0; c < 4; c++) acc[mf][nf][c] = 0.f;

        // prologue: chunk 0 into buffer 0 (128 rows x 8 float4 each for A and B)
        #pragma unroll
        for (int l = 0; l < 4; l++) {
            int f = tid + l * 256;
            int row = f >> 3, kq = f & 7;
            cp16(smemA0 + (uint32_t)(row * ASTRIDE + kq * 4) * 4,
                 &g_res[(size_t)(r0 + row) * CC + kq * 4]);
            cp16(smemB0 + (uint32_t)(row * ASTRIDE + kq * 4) * 4,
                 &cb[(size_t)(n0 + row) * CC + kq * 4]);
        }
        cp_commit();

        for (int kc = 0; kc < CC / BK; ++kc) {
            const int cur = kc & 1;
            cp_wait0();
            __syncthreads();
            if (kc + 1 < CC / BK) {
                const int nb = cur ^ 1;
                const int k0 = (kc + 1) * BK;
                #pragma unroll
                for (int l = 0; l < 4; l++) {
                    int f = tid + l * 256;
                    int row = f >> 3, kq = f & 7;
                    cp16(smemA0 + (uint32_t)(nb * BM * ASTRIDE + row * ASTRIDE + kq * 4) * 4,
                         &g_res[(size_t)(r0 + row) * CC + k0 + kq * 4]);
                    cp16(smemB0 + (uint32_t)(nb * BN * ASTRIDE + row * ASTRIDE + kq * 4) * 4,
                         &cb[(size_t)(n0 + row) * CC + k0 + kq * 4]);
                }
                cp_commit();
            }
            const float* Ab = As + cur * BM * ASTRIDE;
            const float* Bb = Bs + cur * BN * ASTRIDE;
            #pragma unroll
            for (int ks = 0; ks < 4; ++ks) {
                const int kcol = ks * 8 + tig;
                uint32_t afr[2][4], bfr[8][2];
                #pragma unroll
                for (int mf = 0; mf < 2; ++mf) {
                    int base = (wm * 32 + mf * 16 + g) * ASTRIDE + kcol;
                    afr[mf][0] = __float_as_uint(Ab[base]);
                    afr[mf][1] = __float_as_uint(Ab[base + 8 * ASTRIDE]);
                    afr[mf][2] = __float_as_uint(Ab[base + 4]);
                    afr[mf][3] = __float_as_uint(Ab[base + 8 * ASTRIDE + 4]);
                }
                #pragma unroll
                for (int nf = 0; nf < 8; ++nf) {
                    int base = (wn * 64 + nf * 8 + g) * ASTRIDE + kcol;
                    bfr[nf][0] = __float_as_uint(Bb[base]);
                    bfr[nf][1] = __float_as_uint(Bb[base + 4]);
                }
                #pragma unroll
                for (int mf = 0; mf < 2; ++mf)
                    #pragma unroll
                    for (int nf = 0; nf < 8; ++nf)
                        mma_tf32(acc[mf][nf], afr[mf], bfr[nf]);
            }
        }

        // epilogue: d = ||c||^2 - 2*acc ; per-thread best/second
        #pragma unroll
        for (int mf = 0; mf < 2; ++mf)
            #pragma unroll
            for (int nf = 0; nf < 8; ++nf) {
                const int ncol = n0 + wn * 64 + nf * 8 + tig * 2;
                const float nv0 = sNorm[ncol], nv1 = sNorm[ncol + 1];
                upd(bd[mf*2+0], bs[mf*2+0], bi[mf*2+0], fmaf(-2.f, acc[mf][nf][0], nv0), ncol);
                upd(bd[mf*2+0], bs[mf*2+0], bi[mf*2+0], fmaf(-2.f, acc[mf][nf][1], nv1), ncol + 1);
                upd(bd[mf*2+1], bs[mf*2+1], bi[mf*2+1], fmaf(-2.f, acc[mf][nf][2], nv0), ncol);
                upd(bd[mf*2+1], bs[mf*2+1], bi[mf*2+1], fmaf(-2.f, acc[mf][nf][3], nv1), ncol + 1);
            }
    }

    // quad merge (lanes sharing a row differ only in tig = lane&3)
    #pragma unroll
    for (int i = 0; i < 4; i++) {
        #pragma unroll
        for (int off = 1; off <= 2; off <<= 1) {
            float ob = __shfl_xor_sync(0xffffffffu, bd[i], off);
            float os = __shfl_xor_sync(0xffffffffu, bs[i], off);
            int   oi = __shfl_xor_sync(0xffffffffu, bi[i], off);
            merge2(bd[i], bs[i], bi[i], ob, os, oi);
        }
    }
    if (tig == 0) {
        #pragma unroll
        for (int i = 0; i < 4; i++) {
            int lr = wm * 32 + (i >> 1) * 16 + g + (i & 1) * 8;
            sD[wn * 128 + lr] = bd[i];
            sS[wn * 128 + lr] = bs[i];
            sI[wn * 128 + lr] = bi[i];
        }
    }
    __syncthreads();

    if (tid < 128) {
        float b1 = sD[tid], s1 = sS[tid]; int i1 = sI[tid];
        merge2(b1, s1, i1, sD[128 + tid], sS[128 + tid], sI[128 + tid]);
        int flag = (s1 - b1) < DELTA ? 1 : 0;
        sFi[tid] = i1; sFf[tid] = flag;
        idx_out[(size_t)(r0 + tid) * QQ + q] = (float)i1;
        if (flag) { int p = atomicAdd(&g_flagcnt[q], 1); g_flagged[p] = r0 + tid; }
        else atomicAdd(&g_counts[q * KK + i1], 1);
    }
    __syncthreads();

    // fused residual update / loss for unflagged rows
    float lsum = 0.f;
    for (int e = tid; e < BM * 128; e += 256) {
        int m = e >> 7;
        if (!sFf[m]) {
            int c4 = (e & 127) * 4;
            int code = sFi[m];
            float4 rv = *(float4*)&g_res[(size_t)(r0 + m) * CC + c4];
            float4 cv = *(const float4*)&cb[(size_t)code * CC + c4];
            rv.x -= cv.x; rv.y -= cv.y; rv.z -= cv.z; rv.w -= cv.w;
            lsum += rv.x * rv.x + rv.y * rv.y + rv.z * rv.z + rv.w * rv.w;
            *(float4*)&g_res[(size_t)(r0 + m) * CC + c4] = rv;
        }
    }
    sRed[tid] = lsum;
    __syncthreads();
    for (int s = 128; s > 0; s >>= 1) {
        if (tid < s) sRed[tid] += sRed[tid + s];
        __syncthreads();
    }
    if (tid == 0) atomicAdd(&g_loss[q], (double)sRed[0]);
}

// ---------------- exact fallback: 4 flagged rows per block iteration --------
__global__ void __launch_bounds__(256)
vq_fallback_kernel(const float* __restrict__ cb, float* __restrict__ idx_out, int q) {
    __shared__ float srow[4][CC];
    __shared__ int   srows[4];
    __shared__ float swd[8][4];
    __shared__ int   swi[8][4];
    __shared__ int   scode[4];
    __shared__ float sred[256];
    const int tid = threadIdx.x, wid = tid >> 5, lane = tid & 31;
    const int cnt = g_flagcnt[q];

    for (int base = blockIdx.x * 4; base < cnt; base += gridDim.x * 4) {
        const int nr = min(4, cnt - base);
        if (tid < nr) srows[tid] = g_flagged[base + tid];
        __syncthreads();
        for (int e = tid; e < nr * CC; e += 256) {
            int r = e >> 9, c = e & (CC - 1);
            srow[r][c] = g_res[(size_t)srows[r] * CC + c];
        }
        __syncthreads();

        float bdv[4]; int biv[4];
        #pragma unroll
        for (int r = 0; r < 4; r++) { bdv[r] = 3.4e38f; biv[r] = 0x7fffffff; }
        for (int k = wid; k < KK; k += 8) {
            const float* crow = cb + (size_t)k * CC;
            float a0 = 0.f, a1 = 0.f, a2 = 0.f, a3 = 0.f;
            #pragma unroll 4
            for (int c = lane; c < CC; c += 32) {
                float cv = __ldg(&crow[c]);
                a0 = fmaf(srow[0][c], cv, a0);
                a1 = fmaf(srow[1][c], cv, a1);
                a2 = fmaf(srow[2][c], cv, a2);
                a3 = fmaf(srow[3][c], cv, a3);
            }
            #pragma unroll
            for (int off = 16; off > 0; off >>= 1) {
                a0 += __shfl_xor_sync(0xffffffffu, a0, off);
                a1 += __shfl_xor_sync(0xffffffffu, a1, off);
                a2 += __shfl_xor_sync(0xffffffffu, a2, off);
                a3 += __shfl_xor_sync(0xffffffffu, a3, off);
            }
            const float nk = g_cbnorm[q * KK + k];
            float dd[4] = {nk - 2.f * a0, nk - 2.f * a1, nk - 2.f * a2, nk - 2.f * a3};
            #pragma unroll
            for (int r = 0; r < 4; r++)
                if (dd[r] < bdv[r]) { bdv[r] = dd[r]; biv[r] = k; }  // k ascending per warp
        }
        if (lane == 0) {
            #pragma unroll
            for (int r = 0; r < 4; r++) { swd[wid][r] = bdv[r]; swi[wid][r] = biv[r]; }
        }
        __syncthreads();
        if (tid < nr) {
            const int r = tid;
            float b = swd[0][r]; int i = swi[0][r];
            #pragma unroll
            for (int w = 1; w < 8; w++)
                if (swd[w][r] < b || (swd[w][r] == b && swi[w][r] < i)) { b = swd[w][r]; i = swi[w][r]; }
            scode[r] = i;
            idx_out[(size_t)srows[r] * QQ + q] = (float)i;
            atomicAdd(&g_counts[q * KK + i], 1);
        }
        __syncthreads();
        float ls = 0.f;
        for (int e = tid; e < nr * CC; e += 256) {
            int r = e >> 9, c = e & (CC - 1);
            float v = srow[r][c] - cb[(size_t)scode[r] * CC + c];
            g_res[(size_t)srows[r] * CC + c] = v;
            ls += v * v;
        }
        sred[tid] = ls;
        __syncthreads();
        for (int s = 128; s > 0; s >>= 1) {
            if (tid < s) sred[tid] += sred[tid + s];
            __syncthreads();
        }
        if (tid == 0) atomicAdd(&g_loss[q], (double)sred[0]);
        __syncthreads();
    }
}

// ---------------- output: quantized = x - res, back to (N,C,T) --------------
__global__ void output_kernel(const float* __restrict__ x, float* __restrict__ out) {
    __shared__ float tile[32][33];
    int n = blockIdx.z;
    int t0 = blockIdx.x * 32, c0 = blockIdx.y * 32;
    int tx = threadIdx.x;
    #pragma unroll
    for (int i = threadIdx.y; i < 32; i += 8)
        tile[i][tx] = g_res[(size_t)(n * TT + t0 + i) * CC + c0 + tx];
    __syncthreads();
    #pragma unroll
    for (int i = threadIdx.y; i < 32; i += 8) {
        size_t o = (size_t)n * CC * TT + (size_t)(c0 + i) * TT + t0 + tx;
        out[o] = x[o] - tile[tx][i];
    }
}

// ---------------- finalize: loss mean + perplexity mean --------------------
__global__ void finalize_kernel(float* __restrict__ out_scalars) {
    __shared__ float red[256];
    __shared__ float perp_sum_s;
    int tid = threadIdx.x;
    if (tid == 0) perp_sum_s = 0.f;
    __syncthreads();
    for (int q = 0; q < QQ; q++) {
        float h = 0.f;
        for (int k = tid; k < KK; k += 256) {
            float p = (float)g_counts[q * KK + k] / ((float)NT + 1e-10f);
            h += p * logf(p + 1e-7f);
        }
        red[tid] = h;
        __syncthreads();
        for (int s = 128; s > 0; s >>= 1) {
            if (tid < s) red[tid] += red[tid + s];
            __syncthreads();
        }
        if (tid == 0) perp_sum_s += expf(-red[0]);
        __syncthreads();
    }
    if (tid == 0) {
        double ls = 0.0;
        for (int q = 0; q < QQ; q++) ls += g_loss[q];
        out_scalars[0] = (float)(ls / (double)QQ / ((double)NT * (double)CC));
        out_scalars[1] = perp_sum_s / (float)QQ;
    }
}

// ---------------- launch ----------------------------------------------------
#define SMEM_APPROX (2*BM*ASTRIDE*4 + 2*BN*ASTRIDE*4 + KK*4 + 256*4 + 256*4 + 256*4 + 128*4 + 128*4 + 256*4)

extern "C" void kernel_launch(void* const* d_in, const int* in_sizes, int n_in,
                              void* d_out, int out_size) {
    const float* x   = (const float*)d_in[0];   // (64, 512, 512)
    const float* cbs = (const float*)d_in[1];   // (6, 1024, 512)
    float* out = (float*)d_out;
    float* idx_out = out + (size_t)NT * CC;                       // (NT, Q)
    float* scalars = out + (size_t)NT * CC + (size_t)NT * QQ;     // [loss, perp]

    cudaFuncSetAttribute(vq_approx_kernel,
                         cudaFuncAttributeMaxDynamicSharedMemorySize, SMEM_APPROX);

    init_kernel<<<(QQ * KK + 255) / 256, 256>>>();
    cbnorm_kernel<<<(QQ * KK * 32 + 255) / 256, 256>>>(cbs);
    {
        dim3 g(TT / 32, CC / 32, NB), b(32, 8);
        transpose_in_kernel<<<g, b>>>(x);
    }
    for (int q = 0; q < QQ; q++) {
        const float* cb = cbs + (size_t)q * KK * CC;
        vq_approx_kernel<<<NT / BM, 256, SMEM_APPROX>>>(cb, idx_out, q);
        vq_fallback_kernel<<<256, 256>>>(cb, idx_out, q);
    }
    {
        dim3 g(TT / 32, CC / 32, NB), b(32, 8);
        output_kernel<<<g, b>>>(x, out);
    }
    finalize_kernel<<<1, 256>>>(scalars);
}